// round 7
// baseline (speedup 1.0000x reference)
#include <cuda_runtime.h>
#include <cstdint>
#include <cstddef>

#define B_    2
#define N_    2048
#define DIM_  1024
#define H_    16
#define DH_   64
#define MM_   16
#define J_    2064          // N_ + MM_
#define KTOP_ 64
#define SCALE_ 0.125f

// ---------------- static device scratch ----------------
__device__ float g_q   [(size_t)B_*H_*N_*DH_];      // (b,h,i,d)
__device__ float g_k   [(size_t)B_*H_*J_*DH_];      // (b,h,j,d), j<M = mem
__device__ float g_v   [(size_t)B_*H_*J_*DH_];
__device__ float g_smix[(size_t)B_*H_*N_*J_];       // mixed scores (b,k,i,j)
__device__ float g_att [(size_t)B_*N_*DIM_];        // attention output (b,i,k*64+d)

// ---------------- tf32 MMA helpers -----------------------------------------------
__device__ __forceinline__ unsigned to_tf32(float x)
{
    unsigned r;
    asm("cvt.rna.tf32.f32 %0, %1;" : "=r"(r) : "f"(x));
    return r;
}

__device__ __forceinline__ void mma_tf32(float& d0, float& d1, float& d2, float& d3,
                                         unsigned a0, unsigned a1, unsigned a2, unsigned a3,
                                         unsigned b0, unsigned b1)
{
    asm volatile("mma.sync.aligned.m16n8k8.row.col.f32.tf32.tf32.f32 "
                 "{%0,%1,%2,%3}, {%4,%5,%6,%7}, {%8,%9}, {%0,%1,%2,%3};\n"
                 : "+f"(d0), "+f"(d1), "+f"(d2), "+f"(d3)
                 : "r"(a0), "r"(a1), "r"(a2), "r"(a3), "r"(b0), "r"(b1));
}

// =============== 128x128 / BK=16 tf32x3 tensor-MMA GEMM, fused scatter epilogue ==
// MODE 0: C = g_att@B + bias (A param ignored; g_att resolved in device code)
// MODE 1: scatter to g_q   (m=b*2048+i, n=h*64+d)
// MODE 2: scatter to g_k/g_v at row M+i
// Warps: 2(m) x 4(n); each warp computes 64x32 via 4x4 m16n8k8 fragments.
template<int MODE>
__global__ void __launch_bounds__(256) k_gemm(const float* __restrict__ A,
                                              const float* __restrict__ Bm,
                                              const float* __restrict__ bias,
                                              float* __restrict__ C,
                                              int Ndim, int Kdim)
{
    __shared__ unsigned Ah[128][20], Al[128][20];   // A tile [m][k], stride 20
    __shared__ unsigned Bh[16][132], Bl[16][132];   // B tile [k][n], stride 132

    const float* Aeff = (MODE == 0) ? g_att : A;    // device-side symbol resolution

    const int tid  = threadIdx.x;
    const int warp = tid >> 5;
    const int lane = tid & 31;
    const int wm   = warp & 1;          // 0..1 -> 64-row half
    const int wn   = warp >> 1;         // 0..3 -> 32-col quarter
    const int grp  = lane >> 2;         // 0..7
    const int tig  = lane & 3;          // 0..3
    const int m0   = blockIdx.y * 128;
    const int n0   = blockIdx.x * 128;

    const int arow = tid >> 1;              // 0..127
    const int acol = (tid & 1) << 3;        // 0 or 8
    const int bk   = tid >> 5;              // 0..7 (rows bk, bk+8)
    const int bcol = (lane) << 2;           // 0..124

    float acc[4][4][4];
#pragma unroll
    for (int mf = 0; mf < 4; mf++)
#pragma unroll
        for (int nf = 0; nf < 4; nf++)
#pragma unroll
            for (int e = 0; e < 4; e++) acc[mf][nf][e] = 0.f;

    const float* aptr = Aeff + (size_t)(m0 + arow) * Kdim + acol;

    for (int k0 = 0; k0 < Kdim; k0 += 16) {
        // ---- load + split A (each thread: 8 floats) ----
        {
            const float4 a0 = *(const float4*)(aptr + k0);
            const float4 a1 = *(const float4*)(aptr + k0 + 4);
            const float af[8] = {a0.x, a0.y, a0.z, a0.w, a1.x, a1.y, a1.z, a1.w};
#pragma unroll
            for (int e = 0; e < 8; e++) {
                const unsigned h = to_tf32(af[e]);
                Ah[arow][acol + e] = h;
                Al[arow][acol + e] = to_tf32(af[e] - __uint_as_float(h));
            }
        }
        // ---- load + split B (each thread: 2 rows x 4 floats) ----
#pragma unroll
        for (int t = 0; t < 2; t++) {
            const int kr = bk + t * 8;
            const float4 bv = *(const float4*)(Bm + (size_t)(k0 + kr) * Ndim + n0 + bcol);
            const float bf[4] = {bv.x, bv.y, bv.z, bv.w};
            unsigned hv[4], lv[4];
#pragma unroll
            for (int e = 0; e < 4; e++) {
                hv[e] = to_tf32(bf[e]);
                lv[e] = to_tf32(bf[e] - __uint_as_float(hv[e]));
            }
            *(uint4*)&Bh[kr][bcol] = make_uint4(hv[0], hv[1], hv[2], hv[3]);
            *(uint4*)&Bl[kr][bcol] = make_uint4(lv[0], lv[1], lv[2], lv[3]);
        }
        __syncthreads();

#pragma unroll
        for (int ks = 0; ks < 2; ks++) {
            const int kk = ks * 8 + tig;
            unsigned ah[4][4], al[4][4], bh[4][2], bl[4][2];
#pragma unroll
            for (int nf = 0; nf < 4; nf++) {
                const int col = wn * 32 + nf * 8 + grp;
                bh[nf][0] = Bh[kk][col];     bh[nf][1] = Bh[kk + 4][col];
                bl[nf][0] = Bl[kk][col];     bl[nf][1] = Bl[kk + 4][col];
            }
#pragma unroll
            for (int mf = 0; mf < 4; mf++) {
                const int row = wm * 64 + mf * 16 + grp;
                ah[mf][0] = Ah[row][kk];     ah[mf][1] = Ah[row + 8][kk];
                ah[mf][2] = Ah[row][kk + 4]; ah[mf][3] = Ah[row + 8][kk + 4];
                al[mf][0] = Al[row][kk];     al[mf][1] = Al[row + 8][kk];
                al[mf][2] = Al[row][kk + 4]; al[mf][3] = Al[row + 8][kk + 4];
            }
#pragma unroll
            for (int mf = 0; mf < 4; mf++)
#pragma unroll
                for (int nf = 0; nf < 4; nf++) {
                    float* d = acc[mf][nf];
                    mma_tf32(d[0], d[1], d[2], d[3],
                             ah[mf][0], ah[mf][1], ah[mf][2], ah[mf][3],
                             bh[nf][0], bh[nf][1]);
                    mma_tf32(d[0], d[1], d[2], d[3],
                             al[mf][0], al[mf][1], al[mf][2], al[mf][3],
                             bh[nf][0], bh[nf][1]);
                    mma_tf32(d[0], d[1], d[2], d[3],
                             ah[mf][0], ah[mf][1], ah[mf][2], ah[mf][3],
                             bl[nf][0], bl[nf][1]);
                }
        }
        __syncthreads();
    }

    // ---- epilogue: frag (r0,c0),(r0,c0+1),(r1,c0),(r1,c0+1) ----
#pragma unroll
    for (int mf = 0; mf < 4; mf++) {
        const int r0 = m0 + wm * 64 + mf * 16 + grp;
#pragma unroll
        for (int nf = 0; nf < 4; nf++) {
            const int c0 = n0 + wn * 32 + nf * 8 + tig * 2;
            const float* d = acc[mf][nf];
#pragma unroll
            for (int half = 0; half < 2; half++) {
                const int m = r0 + half * 8;
                float2 o = make_float2(d[half * 2], d[half * 2 + 1]);
                if (MODE == 0) {
                    o.x += bias[c0]; o.y += bias[c0 + 1];
                    *(float2*)(C + (size_t)m * Ndim + c0) = o;
                } else {
                    const int b = m >> 11;
                    const int i = m & (N_ - 1);
                    if (MODE == 1) {
                        const int h = c0 >> 6, dd = c0 & 63;
                        *(float2*)(g_q + (((size_t)(b * H_ + h)) * N_ + i) * DH_ + dd) = o;
                    } else {
                        if (c0 < DIM_) {
                            const int h = c0 >> 6, dd = c0 & 63;
                            *(float2*)(g_k + (((size_t)(b * H_ + h)) * J_ + MM_ + i) * DH_ + dd) = o;
                        } else {
                            const int c = c0 - DIM_;
                            const int h = c >> 6, dd = c & 63;
                            *(float2*)(g_v + (((size_t)(b * H_ + h)) * J_ + MM_ + i) * DH_ + dd) = o;
                        }
                    }
                }
            }
        }
    }
}

__global__ void k_fill_mem(const float* __restrict__ mk, const float* __restrict__ mv)
{
    int idx = blockIdx.x * blockDim.x + threadIdx.x;      // B*H*M*DH elems
    int d = idx & 63;
    int r = idx >> 6;
    int j  = r % MM_;  r /= MM_;
    int h  = r % H_;
    int b  = r / H_;
    size_t dst = (((size_t)(b * H_ + h)) * J_ + j) * DH_ + d;
    size_t src = ((size_t)h * MM_ + j) * DH_ + d;
    g_k[dst] = mk[src];
    g_v[dst] = mv[src];
}

// ---------------- fused QK^T + head-mix via tf32x3 MMA (pre-split smem) ----------
// CTA tile: 32(i) x 32(j). 8 warps: warp = (wj<<1)|wi, each owns a 16x8 sub-tile.
// Loaders split Q/K into tf32 hi/lo ONCE per head; inner loop is pure LDS+MMA.
__global__ void __launch_bounds__(256) k_dots_mix(const float* __restrict__ pre)
{
    const int b  = blockIdx.z;
    const int i0 = blockIdx.y * 32;
    const int j0 = blockIdx.x * 32;
    if (j0 > i0 + 31 + MM_) return;     // fully above causal band

    __shared__ unsigned Qh[32][68], Ql[32][68];
    __shared__ unsigned Kh[32][68], Kl[32][68];
    __shared__ float Ppre[H_ * H_];

    const int tid  = threadIdx.x;
    const int warp = tid >> 5;
    const int lane = tid & 31;
    const int wi   = warp & 1;          // i half (0..1)
    const int wj   = warp >> 1;         // j eighth (0..3)
    const int grp  = lane >> 2;         // 0..7
    const int tig  = lane & 3;          // 0..3

    Ppre[tid] = pre[tid];

    const int lr = tid >> 3;            // 0..31 row for tile loads
    const int lc = (tid & 7) << 2;      // 0..28

    const int ri = wi * 16 + grp;       // A-frag row in tile
    const int rj = wj * 8 + grp;        // B-frag row (j) in tile

    float acc[H_][4];
#pragma unroll
    for (int ko = 0; ko < H_; ko++)
#pragma unroll
        for (int e = 0; e < 4; e++) acc[ko][e] = 0.f;

#pragma unroll 1
    for (int h = 0; h < H_; h++) {
        // ---- load + split Q ----
        {
            const float* qrow = g_q + (((size_t)(b * H_ + h)) * N_ + i0 + lr) * DH_;
            const float4 q0 = *(const float4*)(qrow + lc);
            const float4 q1 = *(const float4*)(qrow + lc + 32);
            const float qf[8] = {q0.x, q0.y, q0.z, q0.w, q1.x, q1.y, q1.z, q1.w};
#pragma unroll
            for (int e = 0; e < 8; e++) {
                const int c = (e < 4) ? lc + e : lc + 28 + e;   // lc+e or lc+32+(e-4)
                const unsigned hh = to_tf32(qf[e]);
                Qh[lr][c] = hh;
                Ql[lr][c] = to_tf32(qf[e] - __uint_as_float(hh));
            }
        }
        // ---- load + split K ----
        {
            const int jrow = j0 + lr;
            if (jrow < J_) {
                const float* krow = g_k + (((size_t)(b * H_ + h)) * J_ + jrow) * DH_;
                const float4 k0v = *(const float4*)(krow + lc);
                const float4 k1v = *(const float4*)(krow + lc + 32);
                const float kf[8] = {k0v.x, k0v.y, k0v.z, k0v.w, k1v.x, k1v.y, k1v.z, k1v.w};
#pragma unroll
                for (int e = 0; e < 8; e++) {
                    const int c = (e < 4) ? lc + e : lc + 28 + e;
                    const unsigned hh = to_tf32(kf[e]);
                    Kh[lr][c] = hh;
                    Kl[lr][c] = to_tf32(kf[e] - __uint_as_float(hh));
                }
            } else {
#pragma unroll
                for (int e = 0; e < 8; e++) {
                    const int c = (e < 4) ? lc + e : lc + 28 + e;
                    Kh[lr][c] = 0u;
                    Kl[lr][c] = 0u;
                }
            }
        }
        __syncthreads();

        float s0 = 0.f, s1 = 0.f, s2 = 0.f, s3 = 0.f;
#pragma unroll
        for (int k0 = 0; k0 < DH_; k0 += 8) {
            const unsigned a0h = Qh[ri][k0 + tig],     a1h = Qh[ri + 8][k0 + tig];
            const unsigned a2h = Qh[ri][k0 + tig + 4], a3h = Qh[ri + 8][k0 + tig + 4];
            const unsigned b0h = Kh[rj][k0 + tig],     b1h = Kh[rj][k0 + tig + 4];
            const unsigned a0l = Ql[ri][k0 + tig],     a1l = Ql[ri + 8][k0 + tig];
            const unsigned a2l = Ql[ri][k0 + tig + 4], a3l = Ql[ri + 8][k0 + tig + 4];
            const unsigned b0l = Kl[rj][k0 + tig],     b1l = Kl[rj][k0 + tig + 4];

            mma_tf32(s0, s1, s2, s3, a0h, a1h, a2h, a3h, b0h, b1h);   // hi*hi
            mma_tf32(s0, s1, s2, s3, a0l, a1l, a2l, a3l, b0h, b1h);   // lo*hi
            mma_tf32(s0, s1, s2, s3, a0h, a1h, a2h, a3h, b0l, b1l);   // hi*lo
        }

#pragma unroll
        for (int ko = 0; ko < H_; ko++) {
            const float p = Ppre[h * H_ + ko] * SCALE_;
            acc[ko][0] += p * s0; acc[ko][1] += p * s1;
            acc[ko][2] += p * s2; acc[ko][3] += p * s3;
        }
        __syncthreads();
    }

    // epilogue: D-fragment mapping (rows gi, gi+8; cols gj, gj+1)
    const int gi = i0 + ri;
    const int gj = j0 + wj * 8 + tig * 2;
#pragma unroll
    for (int ko = 0; ko < H_; ko++) {
        const size_t base = (((size_t)(b * H_ + ko)) * N_ + gi) * J_ + gj;
        if (gj < J_) {
            g_smix[base]              = acc[ko][0];
            g_smix[base + 8 * J_]     = acc[ko][2];
        }
        if (gj + 1 < J_) {
            g_smix[base + 1]          = acc[ko][1];
            g_smix[base + 8 * J_ + 1] = acc[ko][3];
        }
    }
}

// ---------------- per-row radix-select top-k + softmax + sparse A*V --------------
__device__ __forceinline__ unsigned fkey(float f)
{
    unsigned u = __float_as_uint(f);
    return (u & 0x80000000u) ? ~u : (u | 0x80000000u);
}
__device__ __forceinline__ float finv(unsigned k)
{
    return (k & 0x80000000u) ? __uint_as_float(k ^ 0x80000000u)
                             : __uint_as_float(~k);
}

__global__ void __launch_bounds__(256) k_topk_av()
{
    const int i  = blockIdx.x;
    const int ko = blockIdx.y;
    const int b  = blockIdx.z;
    const int tid = threadIdx.x;
    const int jmax = min(J_, i + MM_ + 1);

    __shared__ unsigned skeys[J_];
    __shared__ int   sidx[J_];
    __shared__ float swgt[J_];
    __shared__ int   hist[256];
    __shared__ int   suf[256];
    __shared__ unsigned redk[8];
    __shared__ float redf[8];
    __shared__ unsigned s_maxk;
    __shared__ float s_sum;
    __shared__ int   s_bin, s_above, s_cnt;
    __shared__ float accb[4][64];

    const float* row = g_smix + (((size_t)(b * H_ + ko)) * N_ + i) * J_;

    // --- load sweep: keys, max-key, top-byte histogram --------------------------
    hist[tid] = 0;
    __syncthreads();
    unsigned lmax = 0u;
    for (int j = tid; j < jmax; j += 256) {
        unsigned k = fkey(row[j]);
        skeys[j] = k;
        lmax = max(lmax, k);
        atomicAdd(&hist[k >> 24], 1);
    }
#pragma unroll
    for (int o = 16; o > 0; o >>= 1) lmax = max(lmax, __shfl_xor_sync(0xffffffffu, lmax, o));
    if ((tid & 31) == 0) redk[tid >> 5] = lmax;
    __syncthreads();
    if (tid == 0) {
        unsigned m = redk[0];
#pragma unroll
        for (int w = 1; w < 8; w++) m = max(m, redk[w]);
        s_maxk = m;
    }
    __syncthreads();
    const float vmax = finv(s_maxk);

    // --- 4-pass radix select (8 bits per pass, MSB first) -----------------------
    unsigned tkey = 0u;
    if (jmax > KTOP_) {
        unsigned prefix = 0u;
        int kth = KTOP_;
#pragma unroll 1
        for (int pass = 0; pass < 4; pass++) {
            const int shift = 24 - pass * 8;
            if (pass > 0) {
                hist[tid] = 0;
                __syncthreads();
                for (int j = tid; j < jmax; j += 256) {
                    const unsigned k = skeys[j];
                    if ((k >> (shift + 8)) == prefix)
                        atomicAdd(&hist[(k >> shift) & 255u], 1);
                }
                __syncthreads();
            }
            // suffix sum over 256 bins
            suf[tid] = hist[tid];
            __syncthreads();
#pragma unroll 1
            for (int s = 1; s < 256; s <<= 1) {
                int v = suf[tid];
                if (tid + s < 256) v += suf[tid + s];
                __syncthreads();
                suf[tid] = v;
                __syncthreads();
            }
            const int above = (tid == 255) ? 0 : suf[tid + 1];
            if (suf[tid] >= kth && above < kth) { s_bin = tid; s_above = above; }
            __syncthreads();
            prefix = (prefix << 8) | (unsigned)s_bin;
            kth -= s_above;
            __syncthreads();
        }
        tkey = prefix;
    }

    // --- compact survivors + deterministic exp-sum ------------------------------
    if (tid == 0) s_cnt = 0;
    __syncthreads();
    float lsum = 0.f;
    for (int j = tid; j < jmax; j += 256) {
        const unsigned k = skeys[j];
        if (k >= tkey) {
            const float w = expf(finv(k) - vmax);
            lsum += w;
            const int p = atomicAdd(&s_cnt, 1);
            sidx[p] = j;
            swgt[p] = w;
        }
    }
#pragma unroll
    for (int o = 16; o > 0; o >>= 1) lsum += __shfl_xor_sync(0xffffffffu, lsum, o);
    if ((tid & 31) == 0) redf[tid >> 5] = lsum;
    __syncthreads();
    if (tid == 0) {
        float t = 0.f;
#pragma unroll
        for (int w = 0; w < 8; w++) t += redf[w];
        s_sum = t;
    }
    __syncthreads();
    const float sumexp = s_sum;
    const int nsurv = s_cnt;

    // --- gather-weighted sum over surviving v rows ------------------------------
    const int d = tid & 63;
    const int g = tid >> 6;
    float acc = 0.f;
    const float* vb = g_v + ((size_t)(b * H_ + ko)) * J_ * DH_ + d;
    for (int s = g; s < nsurv; s += 4)
        acc += swgt[s] * vb[(size_t)sidx[s] * DH_];
    accb[g][d] = acc;
    __syncthreads();
    if (g == 0) {
        const float tot = accb[0][d] + accb[1][d] + accb[2][d] + accb[3][d];
        g_att[((size_t)(b * N_ + i)) * DIM_ + ko * DH_ + d] = tot / sumexp;
    }
}

// ---------------- launch ---------------------------------------------------------
extern "C" void kernel_launch(void* const* d_in, const int* in_sizes, int n_in,
                              void* d_out, int out_size)
{
    (void)in_sizes; (void)n_in; (void)out_size;
    const float* x    = (const float*)d_in[0];
    const float* Wq   = (const float*)d_in[1];
    const float* Wkv  = (const float*)d_in[2];
    const float* Wo   = (const float*)d_in[3];
    const float* bo   = (const float*)d_in[4];
    const float* pre  = (const float*)d_in[5];
    const float* memk = (const float*)d_in[7];
    const float* memv = (const float*)d_in[8];
    float* out = (float*)d_out;

    k_gemm<1><<<dim3(DIM_ / 128,     (B_ * N_) / 128), 256>>>(x, Wq, nullptr, nullptr, DIM_, DIM_);
    k_gemm<2><<<dim3(2 * DIM_ / 128, (B_ * N_) / 128), 256>>>(x, Wkv, nullptr, nullptr, 2 * DIM_, DIM_);
    k_fill_mem<<<(B_ * H_ * MM_ * DH_) / 256, 256>>>(memk, memv);
    k_dots_mix<<<dim3((J_ + 31) / 32, N_ / 32, B_), 256>>>(pre);
    k_topk_av<<<dim3(N_, H_, B_), 256>>>();
    // MODE 0 reads g_att internally (device-side symbol); A arg is a dummy.
    k_gemm<0><<<dim3(DIM_ / 128, (B_ * N_) / 128), 256>>>(nullptr, Wo, bo, out, DIM_, DIM_);
}

// round 8
// speedup vs baseline: 1.1731x; 1.1731x over previous
#include <cuda_runtime.h>
#include <cstdint>
#include <cstddef>

#define B_    2
#define N_    2048
#define DIM_  1024
#define H_    16
#define DH_   64
#define MM_   16
#define J_    2064          // N_ + MM_
#define KTOP_ 64
#define SCALE_ 0.125f

// ---------------- static device scratch ----------------
__device__ float g_q   [(size_t)B_*H_*N_*DH_];      // (b,h,i,d)
__device__ float g_k   [(size_t)B_*H_*J_*DH_];      // (b,h,j,d), j<M = mem
__device__ float g_v   [(size_t)B_*H_*J_*DH_];
__device__ float g_smix[(size_t)B_*H_*N_*J_];       // mixed scores (b,k,i,j)
__device__ float g_att [(size_t)B_*N_*DIM_];        // attention output (b,i,k*64+d)

// ---------------- tf32 MMA helpers -----------------------------------------------
__device__ __forceinline__ unsigned to_tf32(float x)
{
    unsigned r;
    asm("cvt.rna.tf32.f32 %0, %1;" : "=r"(r) : "f"(x));
    return r;
}

__device__ __forceinline__ void mma_tf32(float& d0, float& d1, float& d2, float& d3,
                                         unsigned a0, unsigned a1, unsigned a2, unsigned a3,
                                         unsigned b0, unsigned b1)
{
    asm volatile("mma.sync.aligned.m16n8k8.row.col.f32.tf32.tf32.f32 "
                 "{%0,%1,%2,%3}, {%4,%5,%6,%7}, {%8,%9}, {%0,%1,%2,%3};\n"
                 : "+f"(d0), "+f"(d1), "+f"(d2), "+f"(d3)
                 : "r"(a0), "r"(a1), "r"(a2), "r"(a3), "r"(b0), "r"(b1));
}

// =============== 128x128 / BK=16 tf32x3 tensor-MMA GEMM, fused scatter epilogue ==
template<int MODE>
__global__ void __launch_bounds__(256) k_gemm(const float* __restrict__ A,
                                              const float* __restrict__ Bm,
                                              const float* __restrict__ bias,
                                              float* __restrict__ C,
                                              int Ndim, int Kdim)
{
    __shared__ unsigned Ah[128][20], Al[128][20];   // A tile [m][k], stride 20
    __shared__ unsigned Bh[16][132], Bl[16][132];   // B tile [k][n], stride 132

    const float* Aeff = (MODE == 0) ? g_att : A;    // device-side symbol resolution

    const int tid  = threadIdx.x;
    const int warp = tid >> 5;
    const int lane = tid & 31;
    const int wm   = warp & 1;
    const int wn   = warp >> 1;
    const int grp  = lane >> 2;
    const int tig  = lane & 3;
    const int m0   = blockIdx.y * 128;
    const int n0   = blockIdx.x * 128;

    const int arow = tid >> 1;
    const int acol = (tid & 1) << 3;
    const int bk   = tid >> 5;
    const int bcol = (lane) << 2;

    float acc[4][4][4];
#pragma unroll
    for (int mf = 0; mf < 4; mf++)
#pragma unroll
        for (int nf = 0; nf < 4; nf++)
#pragma unroll
            for (int e = 0; e < 4; e++) acc[mf][nf][e] = 0.f;

    const float* aptr = Aeff + (size_t)(m0 + arow) * Kdim + acol;

    for (int k0 = 0; k0 < Kdim; k0 += 16) {
        {
            const float4 a0 = *(const float4*)(aptr + k0);
            const float4 a1 = *(const float4*)(aptr + k0 + 4);
            const float af[8] = {a0.x, a0.y, a0.z, a0.w, a1.x, a1.y, a1.z, a1.w};
#pragma unroll
            for (int e = 0; e < 8; e++) {
                const unsigned h = to_tf32(af[e]);
                Ah[arow][acol + e] = h;
                Al[arow][acol + e] = to_tf32(af[e] - __uint_as_float(h));
            }
        }
#pragma unroll
        for (int t = 0; t < 2; t++) {
            const int kr = bk + t * 8;
            const float4 bv = *(const float4*)(Bm + (size_t)(k0 + kr) * Ndim + n0 + bcol);
            const float bf[4] = {bv.x, bv.y, bv.z, bv.w};
            unsigned hv[4], lv[4];
#pragma unroll
            for (int e = 0; e < 4; e++) {
                hv[e] = to_tf32(bf[e]);
                lv[e] = to_tf32(bf[e] - __uint_as_float(hv[e]));
            }
            *(uint4*)&Bh[kr][bcol] = make_uint4(hv[0], hv[1], hv[2], hv[3]);
            *(uint4*)&Bl[kr][bcol] = make_uint4(lv[0], lv[1], lv[2], lv[3]);
        }
        __syncthreads();

#pragma unroll
        for (int ks = 0; ks < 2; ks++) {
            const int kk = ks * 8 + tig;
            unsigned ah[4][4], al[4][4], bh[4][2], bl[4][2];
#pragma unroll
            for (int nf = 0; nf < 4; nf++) {
                const int col = wn * 32 + nf * 8 + grp;
                bh[nf][0] = Bh[kk][col];     bh[nf][1] = Bh[kk + 4][col];
                bl[nf][0] = Bl[kk][col];     bl[nf][1] = Bl[kk + 4][col];
            }
#pragma unroll
            for (int mf = 0; mf < 4; mf++) {
                const int row = wm * 64 + mf * 16 + grp;
                ah[mf][0] = Ah[row][kk];     ah[mf][1] = Ah[row + 8][kk];
                ah[mf][2] = Ah[row][kk + 4]; ah[mf][3] = Ah[row + 8][kk + 4];
                al[mf][0] = Al[row][kk];     al[mf][1] = Al[row + 8][kk];
                al[mf][2] = Al[row][kk + 4]; al[mf][3] = Al[row + 8][kk + 4];
            }
#pragma unroll
            for (int mf = 0; mf < 4; mf++)
#pragma unroll
                for (int nf = 0; nf < 4; nf++) {
                    float* d = acc[mf][nf];
                    mma_tf32(d[0], d[1], d[2], d[3],
                             ah[mf][0], ah[mf][1], ah[mf][2], ah[mf][3],
                             bh[nf][0], bh[nf][1]);
                    mma_tf32(d[0], d[1], d[2], d[3],
                             al[mf][0], al[mf][1], al[mf][2], al[mf][3],
                             bh[nf][0], bh[nf][1]);
                    mma_tf32(d[0], d[1], d[2], d[3],
                             ah[mf][0], ah[mf][1], ah[mf][2], ah[mf][3],
                             bl[nf][0], bl[nf][1]);
                }
        }
        __syncthreads();
    }

#pragma unroll
    for (int mf = 0; mf < 4; mf++) {
        const int r0 = m0 + wm * 64 + mf * 16 + grp;
#pragma unroll
        for (int nf = 0; nf < 4; nf++) {
            const int c0 = n0 + wn * 32 + nf * 8 + tig * 2;
            const float* d = acc[mf][nf];
#pragma unroll
            for (int half = 0; half < 2; half++) {
                const int m = r0 + half * 8;
                float2 o = make_float2(d[half * 2], d[half * 2 + 1]);
                if (MODE == 0) {
                    o.x += bias[c0]; o.y += bias[c0 + 1];
                    *(float2*)(C + (size_t)m * Ndim + c0) = o;
                } else {
                    const int b = m >> 11;
                    const int i = m & (N_ - 1);
                    if (MODE == 1) {
                        const int h = c0 >> 6, dd = c0 & 63;
                        *(float2*)(g_q + (((size_t)(b * H_ + h)) * N_ + i) * DH_ + dd) = o;
                    } else {
                        if (c0 < DIM_) {
                            const int h = c0 >> 6, dd = c0 & 63;
                            *(float2*)(g_k + (((size_t)(b * H_ + h)) * J_ + MM_ + i) * DH_ + dd) = o;
                        } else {
                            const int c = c0 - DIM_;
                            const int h = c >> 6, dd = c & 63;
                            *(float2*)(g_v + (((size_t)(b * H_ + h)) * J_ + MM_ + i) * DH_ + dd) = o;
                        }
                    }
                }
            }
        }
    }
}

__global__ void k_fill_mem(const float* __restrict__ mk, const float* __restrict__ mv)
{
    int idx = blockIdx.x * blockDim.x + threadIdx.x;      // B*H*M*DH elems
    int d = idx & 63;
    int r = idx >> 6;
    int j  = r % MM_;  r /= MM_;
    int h  = r % H_;
    int b  = r / H_;
    size_t dst = (((size_t)(b * H_ + h)) * J_ + j) * DH_ + d;
    size_t src = ((size_t)h * MM_ + j) * DH_ + d;
    g_k[dst] = mk[src];
    g_v[dst] = mv[src];
}

// ---------------- fused QK^T + head-mix via tf32x3 MMA (round-6 body) ------------
__global__ void __launch_bounds__(256) k_dots_mix(const float* __restrict__ pre)
{
    const int b  = blockIdx.z;
    const int i0 = blockIdx.y * 32;
    const int j0 = blockIdx.x * 32;
    if (j0 > i0 + 31 + MM_) return;     // fully above causal band

    __shared__ __align__(16) float Qs[32][68];
    __shared__ __align__(16) float Ks[32][68];
    __shared__ float Ppre[H_ * H_];

    const int tid  = threadIdx.x;
    const int warp = tid >> 5;
    const int lane = tid & 31;
    const int wi   = warp & 1;
    const int wj   = warp >> 1;
    const int grp  = lane >> 2;
    const int tig  = lane & 3;

    Ppre[tid] = pre[tid];

    const int lr = tid >> 3;
    const int lc = (tid & 7) << 2;

    const int ri = wi * 16 + grp;
    const int rj = wj * 8 + grp;

    float acc[H_][4];
#pragma unroll
    for (int ko = 0; ko < H_; ko++)
#pragma unroll
        for (int e = 0; e < 4; e++) acc[ko][e] = 0.f;

#pragma unroll 1
    for (int h = 0; h < H_; h++) {
        const float* qrow = g_q + (((size_t)(b * H_ + h)) * N_ + i0 + lr) * DH_;
        *(float4*)&Qs[lr][lc]      = *(const float4*)(qrow + lc);
        *(float4*)&Qs[lr][lc + 32] = *(const float4*)(qrow + lc + 32);
        const int jrow = j0 + lr;
        if (jrow < J_) {
            const float* krow = g_k + (((size_t)(b * H_ + h)) * J_ + jrow) * DH_;
            *(float4*)&Ks[lr][lc]      = *(const float4*)(krow + lc);
            *(float4*)&Ks[lr][lc + 32] = *(const float4*)(krow + lc + 32);
        } else {
            float4 z = make_float4(0.f, 0.f, 0.f, 0.f);
            *(float4*)&Ks[lr][lc] = z;
            *(float4*)&Ks[lr][lc + 32] = z;
        }
        __syncthreads();

        float s0 = 0.f, s1 = 0.f, s2 = 0.f, s3 = 0.f;
#pragma unroll
        for (int k0 = 0; k0 < DH_; k0 += 8) {
            const float a0f = Qs[ri]    [k0 + tig];
            const float a1f = Qs[ri + 8][k0 + tig];
            const float a2f = Qs[ri]    [k0 + tig + 4];
            const float a3f = Qs[ri + 8][k0 + tig + 4];
            const float b0f = Ks[rj][k0 + tig];
            const float b1f = Ks[rj][k0 + tig + 4];

            const unsigned a0h = to_tf32(a0f), a1h = to_tf32(a1f);
            const unsigned a2h = to_tf32(a2f), a3h = to_tf32(a3f);
            const unsigned b0h = to_tf32(b0f), b1h = to_tf32(b1f);
            const unsigned a0l = to_tf32(a0f - __uint_as_float(a0h));
            const unsigned a1l = to_tf32(a1f - __uint_as_float(a1h));
            const unsigned a2l = to_tf32(a2f - __uint_as_float(a2h));
            const unsigned a3l = to_tf32(a3f - __uint_as_float(a3h));
            const unsigned b0l = to_tf32(b0f - __uint_as_float(b0h));
            const unsigned b1l = to_tf32(b1f - __uint_as_float(b1h));

            mma_tf32(s0, s1, s2, s3, a0h, a1h, a2h, a3h, b0h, b1h);   // hi*hi
            mma_tf32(s0, s1, s2, s3, a0l, a1l, a2l, a3l, b0h, b1h);   // lo*hi
            mma_tf32(s0, s1, s2, s3, a0h, a1h, a2h, a3h, b0l, b1l);   // hi*lo
        }

#pragma unroll
        for (int ko = 0; ko < H_; ko++) {
            const float p = Ppre[h * H_ + ko] * SCALE_;
            acc[ko][0] += p * s0; acc[ko][1] += p * s1;
            acc[ko][2] += p * s2; acc[ko][3] += p * s3;
        }
        __syncthreads();
    }

    const int gi = i0 + ri;
    const int gj = j0 + wj * 8 + tig * 2;
#pragma unroll
    for (int ko = 0; ko < H_; ko++) {
        const size_t base = (((size_t)(b * H_ + ko)) * N_ + gi) * J_ + gj;
        if (gj < J_) {
            g_smix[base]              = acc[ko][0];
            g_smix[base + 8 * J_]     = acc[ko][2];
        }
        if (gj + 1 < J_) {
            g_smix[base + 1]          = acc[ko][1];
            g_smix[base + 8 * J_ + 1] = acc[ko][3];
        }
    }
}

// ---------------- per-row top-k + softmax + sparse A*V ---------------------------
__device__ __forceinline__ unsigned fkey(float f)
{
    unsigned u = __float_as_uint(f);
    return (u & 0x80000000u) ? ~u : (u | 0x80000000u);
}
__device__ __forceinline__ float finv(unsigned k)
{
    return (k & 0x80000000u) ? __uint_as_float(k ^ 0x80000000u)
                             : __uint_as_float(~k);
}

// single-warp suffix-scan over 256 bins; finds bin B with suffix(B) >= kth > suffix(B+1)
__device__ __forceinline__ void scan_bins(const int* hist, int kth, int tid,
                                          int* s_bin, int* s_above)
{
    if (tid < 32) {
        int loc[8];
        int sum = 0;
#pragma unroll
        for (int e = 0; e < 8; e++) { loc[e] = hist[tid * 8 + e]; sum += loc[e]; }
        int v = sum;
#pragma unroll
        for (int o = 1; o < 32; o <<= 1) {
            const int u = __shfl_down_sync(0xffffffffu, v, o);
            if (tid + o < 32) v += u;
        }
        const int after_lane = v - sum;        // count in lanes > tid
        int run = after_lane;
        int sfx[8];
#pragma unroll
        for (int e = 7; e >= 0; e--) { run += loc[e]; sfx[e] = run; }
#pragma unroll
        for (int e = 0; e < 8; e++) {
            const int above = (e == 7) ? after_lane : sfx[e + 1];
            if (sfx[e] >= kth && above < kth) { *s_bin = tid * 8 + e; *s_above = above; }
        }
    }
}

__global__ void __launch_bounds__(256) k_topk_av()
{
    const int i  = blockIdx.x;
    const int ko = blockIdx.y;
    const int b  = blockIdx.z;
    const int tid = threadIdx.x;
    const int lane = tid & 31;
    const int jmax = min(J_, i + MM_ + 1);

    __shared__ unsigned skeys[J_];
    __shared__ int   sidx[J_];       // survivor indices; reused as candB
    __shared__ float swgt[J_];       // survivor weights; reused as candA
    __shared__ int   hist[256];
    __shared__ unsigned redk[8];
    __shared__ float redf[8];
    __shared__ unsigned s_maxk, s_tkey;
    __shared__ float s_sum;
    __shared__ int   s_bin, s_above, s_cnt;
    __shared__ float accb[4][64];

    const float* row = g_smix + (((size_t)(b * H_ + ko)) * N_ + i) * J_;

    // --- load sweep fused with top-byte histogram (warp-aggregated atomics) -----
    hist[tid] = 0;
    __syncthreads();
    unsigned lmax = 0u;
    const int nIter = (jmax + 255) >> 8;
    for (int it = 0; it < nIter; it++) {
        const int j = tid + (it << 8);
        const bool valid = j < jmax;
        unsigned k = 0u;
        if (valid) {
            k = fkey(row[j]);
            skeys[j] = k;
            lmax = max(lmax, k);
        }
        const unsigned bin = valid ? (k >> 24) : 300u;     // sentinel for invalid
        const unsigned mmask = __match_any_sync(0xffffffffu, bin);
        if (valid && (mmask & ((1u << lane) - 1u)) == 0u)  // lowest lane = leader
            atomicAdd(&hist[bin], __popc(mmask));
    }
#pragma unroll
    for (int o = 16; o > 0; o >>= 1) lmax = max(lmax, __shfl_xor_sync(0xffffffffu, lmax, o));
    if (lane == 0) redk[tid >> 5] = lmax;
    __syncthreads();
    if (tid == 0) {
        unsigned m = redk[0];
#pragma unroll
        for (int w = 1; w < 8; w++) m = max(m, redk[w]);
        s_maxk = m;
    }
    __syncthreads();
    const float vmax = finv(s_maxk);

    // --- exact K-th largest key: bin scan + boundary-bin candidate select -------
    unsigned tkey = 0u;
    if (jmax > KTOP_) {
        scan_bins(hist, KTOP_, tid, &s_bin, &s_above);
        __syncthreads();
        const int b0 = s_bin;
        int kth = KTOP_ - s_above;

        if (tid == 0) s_cnt = 0;
        __syncthreads();
        unsigned* candA = (unsigned*)swgt;
        unsigned* candB = (unsigned*)sidx;
        for (int j = tid; j < jmax; j += 256) {
            const unsigned k = skeys[j];
            if ((k >> 24) == (unsigned)b0) candA[atomicAdd(&s_cnt, 1)] = k;
        }
        __syncthreads();
        int c = s_cnt;
        unsigned* cur = candA;
        unsigned* alt = candB;
        int shift = 16;
        while (c > 48 && shift >= 0) {
            hist[tid] = 0;
            __syncthreads();
            for (int t = tid; t < c; t += 256)
                atomicAdd(&hist[(cur[t] >> shift) & 255u], 1);
            __syncthreads();
            scan_bins(hist, kth, tid, &s_bin, &s_above);
            __syncthreads();
            const int bsel = s_bin;
            kth -= s_above;
            if (tid == 0) s_cnt = 0;
            __syncthreads();
            for (int t = tid; t < c; t += 256)
                if (((cur[t] >> shift) & 255u) == (unsigned)bsel)
                    alt[atomicAdd(&s_cnt, 1)] = cur[t];
            __syncthreads();
            c = s_cnt;
            unsigned* tmp = cur; cur = alt; alt = tmp;
            shift -= 8;
        }
        if (shift < 0) {
            if (tid == 0) s_tkey = cur[0];          // all remaining keys identical
        } else {
            // exact rank-count select among c (<=48) candidates
            for (int t = tid; t < c; t += 256) {
                const unsigned x = cur[t];
                int gt = 0, ge = 0;
                for (int u = 0; u < c; u++) { gt += (cur[u] > x); ge += (cur[u] >= x); }
                if (gt < kth && ge >= kth) s_tkey = x;
            }
        }
        __syncthreads();
        tkey = s_tkey;
    }

    // --- compact survivors + deterministic exp-sum ------------------------------
    if (tid == 0) s_cnt = 0;
    __syncthreads();
    float lsum = 0.f;
    for (int j = tid; j < jmax; j += 256) {
        const unsigned k = skeys[j];
        if (k >= tkey) {
            const float w = expf(finv(k) - vmax);
            lsum += w;
            const int p = atomicAdd(&s_cnt, 1);
            sidx[p] = j;
            swgt[p] = w;
        }
    }
#pragma unroll
    for (int o = 16; o > 0; o >>= 1) lsum += __shfl_xor_sync(0xffffffffu, lsum, o);
    if (lane == 0) redf[tid >> 5] = lsum;
    __syncthreads();
    if (tid == 0) {
        float t = 0.f;
#pragma unroll
        for (int w = 0; w < 8; w++) t += redf[w];
        s_sum = t;
    }
    __syncthreads();
    const float sumexp = s_sum;
    const int nsurv = s_cnt;

    // --- gather-weighted sum over surviving v rows ------------------------------
    const int d = tid & 63;
    const int g = tid >> 6;
    float acc = 0.f;
    const float* vb = g_v + ((size_t)(b * H_ + ko)) * J_ * DH_ + d;
    for (int s = g; s < nsurv; s += 4)
        acc += swgt[s] * vb[(size_t)sidx[s] * DH_];
    accb[g][d] = acc;
    __syncthreads();
    if (g == 0) {
        const float tot = accb[0][d] + accb[1][d] + accb[2][d] + accb[3][d];
        g_att[((size_t)(b * N_ + i)) * DIM_ + ko * DH_ + d] = tot / sumexp;
    }
}

// ---------------- launch ---------------------------------------------------------
extern "C" void kernel_launch(void* const* d_in, const int* in_sizes, int n_in,
                              void* d_out, int out_size)
{
    (void)in_sizes; (void)n_in; (void)out_size;
    const float* x    = (const float*)d_in[0];
    const float* Wq   = (const float*)d_in[1];
    const float* Wkv  = (const float*)d_in[2];
    const float* Wo   = (const float*)d_in[3];
    const float* bo   = (const float*)d_in[4];
    const float* pre  = (const float*)d_in[5];
    const float* memk = (const float*)d_in[7];
    const float* memv = (const float*)d_in[8];
    float* out = (float*)d_out;

    k_gemm<1><<<dim3(DIM_ / 128,     (B_ * N_) / 128), 256>>>(x, Wq, nullptr, nullptr, DIM_, DIM_);
    k_gemm<2><<<dim3(2 * DIM_ / 128, (B_ * N_) / 128), 256>>>(x, Wkv, nullptr, nullptr, 2 * DIM_, DIM_);
    k_fill_mem<<<(B_ * H_ * MM_ * DH_) / 256, 256>>>(memk, memv);
    k_dots_mix<<<dim3((J_ + 31) / 32, N_ / 32, B_), 256>>>(pre);
    k_topk_av<<<dim3(N_, H_, B_), 256>>>();
    // MODE 0 reads g_att internally (device-side symbol); A arg is a dummy.
    k_gemm<0><<<dim3(DIM_ / 128, (B_ * N_) / 128), 256>>>(nullptr, Wo, bo, out, DIM_, DIM_);
}